// round 8
// baseline (speedup 1.0000x reference)
#include <cuda_runtime.h>

#define B  4
#define C  84
#define CR 80          // channels participating in max (84 - 4)
#define H  512
#define W  512
#define HW (H * W)

// 4 MB scratch for per-pixel max-probs (device global: allocation-free rule)
__device__ float g_probs[B * HW];

// ---------------------------------------------------------------------------
// Kernel 1: probs[b,h,w] = max_{c<80} points[b,c,h,w]
// One thread per float4 (4 consecutive x pixels). Loads are 16B, fully
// coalesced per channel; channel stride is HW floats. Streaming loads
// (__ldcs): this 335 MB read is never reused — keep L2 clean for probs.
// ---------------------------------------------------------------------------
__global__ void __launch_bounds__(256) max_over_channels_kernel(
    const float* __restrict__ points)
{
    int i4 = blockIdx.x * blockDim.x + threadIdx.x;   // float4 index in [0, B*HW/4)
    const int N4 = B * HW / 4;
    if (i4 >= N4) return;

    int b    = i4 / (HW / 4);
    int pix4 = i4 % (HW / 4);

    const float4* base = reinterpret_cast<const float4*>(
        points + (size_t)b * C * HW) + pix4;

    float4 m = __ldcs(base);
    #pragma unroll 8
    for (int c = 1; c < CR; c++) {
        float4 v = __ldcs(base + (size_t)c * (HW / 4));
        m.x = fmaxf(m.x, v.x);
        m.y = fmaxf(m.y, v.y);
        m.z = fmaxf(m.z, v.z);
        m.w = fmaxf(m.w, v.w);
    }
    reinterpret_cast<float4*>(g_probs)[i4] = m;
}

// ---------------------------------------------------------------------------
// Kernel 2: per-pixel 3x3 NMS mask on probs, then out = points * mask for all
// 84 channels. One block per (b, h) row: 128 threads x 4 pixels = 512 = W.
// Reference semantics (padded window, center idx = 4):
//   idx < 4  (row above, and left neighbor)  -> p >  nb
//   idx > 4  (right neighbor, and row below) -> p >= nb
// Out-of-image neighbors are the pad value 0.0f.
// Output stores are streaming (__stcs): out is never re-read.
// ---------------------------------------------------------------------------
__global__ void __launch_bounds__(128) nms_multiply_kernel(
    const float* __restrict__ points, float* __restrict__ out)
{
    const int h = blockIdx.x;
    const int b = blockIdx.y;
    const int tid = threadIdx.x;           // 0..127

    __shared__ float s[3][W + 2];          // [row-1, row, row+1], halo of 1, zero-padded

    // Load the 3 prob rows (zero rows outside the image); probs is 4 MB and
    // each row is read by 3 blocks -> L2 hits.
    #pragma unroll
    for (int r = 0; r < 3; r++) {
        int hh = h + r - 1;
        float4 v = make_float4(0.f, 0.f, 0.f, 0.f);
        if (hh >= 0 && hh < H) {
            v = __ldg(reinterpret_cast<const float4*>(
                    g_probs + (size_t)b * HW + (size_t)hh * W) + tid);
        }
        int x = tid * 4;
        s[r][1 + x + 0] = v.x;
        s[r][1 + x + 1] = v.y;
        s[r][1 + x + 2] = v.z;
        s[r][1 + x + 3] = v.w;
    }
    if (tid < 3) {                         // left/right zero padding
        s[tid][0]     = 0.f;
        s[tid][W + 1] = 0.f;
    }
    __syncthreads();

    // Compute mask for this thread's 4 pixels
    float msk[4];
    const int x0 = tid * 4;
    #pragma unroll
    for (int k = 0; k < 4; k++) {
        int x = x0 + k;                    // smem center column is x+1
        float p = s[1][x + 1];
        bool m =
            (p >  s[0][x    ]) &&          // idx 0
            (p >  s[0][x + 1]) &&          // idx 1
            (p >  s[0][x + 2]) &&          // idx 2
            (p >  s[1][x    ]) &&          // idx 3 (left)
            (p >= s[1][x + 2]) &&          // idx 5 (right)
            (p >= s[2][x    ]) &&          // idx 6
            (p >= s[2][x + 1]) &&          // idx 7
            (p >= s[2][x + 2]);            // idx 8
        msk[k] = m ? 1.0f : 0.0f;
    }

    // Multiply all 84 channels of this row by the mask (float4 per thread)
    const size_t row_off = (size_t)b * C * HW + (size_t)h * W;
    const float4* pin  = reinterpret_cast<const float4*>(points + row_off) + tid;
    float4*       pout = reinterpret_cast<float4*>(out + row_off) + tid;

    #pragma unroll 4
    for (int c = 0; c < C; c++) {
        float4 v = __ldcs(pin + (size_t)c * (HW / 4));
        v.x *= msk[0];
        v.y *= msk[1];
        v.z *= msk[2];
        v.w *= msk[3];
        __stcs(pout + (size_t)c * (HW / 4), v);
    }
}

// ---------------------------------------------------------------------------
extern "C" void kernel_launch(void* const* d_in, const int* in_sizes, int n_in,
                              void* d_out, int out_size)
{
    const float* points = (const float*)d_in[0];
    float* out = (float*)d_out;

    // K1: one thread per float4 over B*HW pixels
    const int N4 = B * HW / 4;
    max_over_channels_kernel<<<(N4 + 255) / 256, 256>>>(points);

    // K2: one block per (b, h) row
    dim3 grid(H, B);
    nms_multiply_kernel<<<grid, 128>>>(points, out);
}